// round 14
// baseline (speedup 1.0000x reference)
#include <cuda_runtime.h>
#include <cuda_fp16.h>
#include <cstdint>
#include <math.h>

#define BATCH 2
#define SEQ   1024
#define EMB   1024
#define NH    16
#define HS    64
#define BD    16
#define DELTA 64
#define TTILE 32
#define NROWS (TTILE + DELTA - 1)   // 95
#define MTOT  (BATCH * SEQ)         // 2048
#define NDV   1280                  // disp (256) ++ val (1024) columns

// ---------------- scratch (static device memory; no allocs) ----------------
__device__ float g_dv [MTOT * NDV];                // [disp | val] fp32
__device__ float g_pos[DELTA * BD];
__device__ __half g_xhi [MTOT * EMB];
__device__ __half g_athi[MTOT * EMB];
__device__ __half g_bthi[NDV * EMB];               // [W_disp^T ++ W_val^T]
__device__ __half g_cthi[EMB * EMB];               // W_cproj^T

// ---------------- helpers (pd_ prefix: no vendor-header collisions) --------
typedef unsigned long long u64;

__device__ __forceinline__ u64 pd_dupf(float v) {
    u64 r; asm("mov.b64 %0, {%1, %1};" : "=l"(r) : "f"(v)); return r;
}
__device__ __forceinline__ void pd_unpack2(u64 v, float& a, float& b) {
    asm("mov.b64 {%0, %1}, %2;" : "=f"(a), "=f"(b) : "l"(v));
}
__device__ __forceinline__ u64 pd_fma2(u64 a, u64 b, u64 c) {
    u64 r; asm("fma.rn.f32x2 %0, %1, %2, %3;" : "=l"(r) : "l"(a), "l"(b), "l"(c)); return r;
}
__device__ __forceinline__ float pd_tanhf(float x) {
    float r; asm("tanh.approx.f32 %0, %1;" : "=f"(r) : "f"(x)); return r;
}
__device__ __forceinline__ float pd_ex2(float x) {
    float r; asm("ex2.approx.f32 %0, %1;" : "=f"(r) : "f"(x)); return r;
}
__device__ __forceinline__ uint32_t pd_smem_u32(const void* p) {
    uint32_t a;
    asm("{ .reg .u64 t; cvta.to.shared.u64 t, %1; cvt.u32.u64 %0, t; }" : "=r"(a) : "l"(p));
    return a;
}
__device__ __forceinline__ void pd_cp16(uint32_t dst, const void* src) {
    asm volatile("{ .reg .u64 g; cvta.to.global.u64 g, %1; cp.async.cg.shared.global [%0], [g], 16; }"
                 :: "r"(dst), "l"(src) : "memory");
}
__device__ __forceinline__ void pd_cp_commit() { asm volatile("cp.async.commit_group;" ::: "memory"); }
__device__ __forceinline__ void pd_cp_wait(int pending) {
    if (pending) asm volatile("cp.async.wait_group 1;" ::: "memory");
    else         asm volatile("cp.async.wait_group 0;" ::: "memory");
}

__device__ __forceinline__ void pd_split2h(float a, float b, uint32_t& hi, uint32_t& lo) {
    __half2 h2 = __floats2half2_rn(a, b);
    float ra = a - __half2float(h2.x);
    float rb = b - __half2float(h2.y);
    __half2 l2 = __floats2half2_rn(ra, rb);
    hi = *reinterpret_cast<uint32_t*>(&h2);
    lo = *reinterpret_cast<uint32_t*>(&l2);
}

__device__ __forceinline__ void pd_mma_fp16(float* c, const uint32_t* a, const uint32_t* b) {
    asm volatile(
        "mma.sync.aligned.m16n8k16.row.col.f32.f16.f16.f32 "
        "{%0,%1,%2,%3}, {%4,%5,%6,%7}, {%8,%9}, {%0,%1,%2,%3};"
        : "+f"(c[0]), "+f"(c[1]), "+f"(c[2]), "+f"(c[3])
        : "r"(a[0]), "r"(a[1]), "r"(a[2]), "r"(a[3]), "r"(b[0]), "r"(b[1]));
}

#define PD_LDSM_X4(r, a) \
    asm volatile("ldmatrix.sync.aligned.m8n8.x4.shared.b16 {%0,%1,%2,%3}, [%4];" \
                 : "=r"((r)[0]), "=r"((r)[1]), "=r"((r)[2]), "=r"((r)[3]) : "r"(a))
#define PD_LDSM_X2T(r, a) \
    asm volatile("ldmatrix.sync.aligned.m8n8.x2.trans.shared.b16 {%0,%1}, [%2];" \
                 : "=r"((r)[0]), "=r"((r)[1]) : "r"(a))

// ---------------- conversion kernels ----------------
__global__ __launch_bounds__(512) void split_x_kernel(const float* __restrict__ x) {
    size_t i = (size_t)blockIdx.x * 512 + threadIdx.x;   // over 512K float4
    float4 v = ((const float4*)x)[i];
    __half2 a = __floats2half2_rn(v.x, v.y);
    __half2 b = __floats2half2_rn(v.z, v.w);
    ((__half2*)g_xhi)[2 * i]     = a;
    ((__half2*)g_xhi)[2 * i + 1] = b;
}

// transpose+convert; block (0,0) also computes pos = rel_pos_emb @ W_pos.
__global__ void splitT_kernel(const float* __restrict__ Wd,
                              const float* __restrict__ Wv,
                              const float* __restrict__ Wc,
                              const float* __restrict__ rel,
                              const float* __restrict__ Wp)
{
    __shared__ float tile[32][33];
    const int k0 = blockIdx.y * 32;
    const int n0 = blockIdx.x * 32;
    const int tx = threadIdx.x, ty = threadIdx.y;   // 32 x 8
    const int tid = ty * 32 + tx;

    if (blockIdx.x == 0 && blockIdx.y == 0) {
#pragma unroll
        for (int q = 0; q < 4; q++) {
            int i = tid + q * 256;     // over 1024 outputs
            int j = i >> 4, c = i & 15;
            float s = 0.f;
#pragma unroll
            for (int k = 0; k < BD; k++)
                s = fmaf(rel[j * BD + k], Wp[k * BD + c], s);
            g_pos[i] = s;
        }
    }

#pragma unroll
    for (int q = 0; q < 4; q++) {
        int k = k0 + ty + 8 * q;
        int n = n0 + tx;
        float v;
        if (n < 256)        v = Wd[(size_t)k * 256 + n];
        else if (n < 1280)  v = Wv[(size_t)k * EMB + (n - 256)];
        else                v = Wc[(size_t)k * EMB + (n - 1280)];
        tile[ty + 8 * q][tx] = v;
    }
    __syncthreads();
#pragma unroll
    for (int q = 0; q < 4; q++) {
        int n = n0 + ty + 8 * q;
        int k = k0 + tx;
        __half hv = __float2half_rn(tile[tx][ty + 8 * q]);
        if (n < 1280) g_bthi[(size_t)n * EMB + k] = hv;
        else          g_cthi[(size_t)(n - 1280) * EMB + k] = hv;
    }
}

// ---------------- fp16 HMMA GEMM: K-chunk 128, double buffered ----------------
#define ROWB 272        // 128 halfs (256 B) + 16 B pad; 68 words ≡ 4 mod 32: conflict-free
#define KCH  128
#define NSTG (EMB / KCH)   // 8

template<int BM, int BN, int THREADS, int WN>
__global__ __launch_bounds__(THREADS) void gemm_kernel(
    const __half* __restrict__ Ahi, const __half* __restrict__ Bhi,
    float* __restrict__ C, int ldc)
{
    extern __shared__ __align__(16) char sm[];
    const uint32_t sbase = pd_smem_u32(sm);
    const int tid  = threadIdx.x;
    const int wid  = tid >> 5;
    const int lane = tid & 31;
    const int wm   = wid / WN;
    const int wn   = wid % WN;
    const int m0 = blockIdx.y * BM;
    const int n0 = blockIdx.x * BN;
    const int r4 = lane >> 2;
    const int t  = lane & 3;

    constexpr int WARP_N = BN / WN;        // 32 or 40
    constexpr int NFRAG  = WARP_N / 8;     // 4 or 5
    const int BUFSZ = (BM + BN) * ROWB;

    float acc[2][NFRAG][4];
#pragma unroll
    for (int i = 0; i < 2; i++)
#pragma unroll
        for (int j = 0; j < NFRAG; j++)
#pragma unroll
            for (int q = 0; q < 4; q++) acc[i][j][q] = 0.f;

    auto load_stage = [&](int s) {
        const int buf = s & 1;
        const int k0 = s * KCH;
        uint32_t base = sbase + buf * BUFSZ;
#pragma unroll 4
        for (int i = tid; i < BM * 16; i += THREADS) {
            int row = i >> 4, seg = i & 15;
            pd_cp16(base + row * ROWB + seg * 16,
                    Ahi + (size_t)(m0 + row) * EMB + k0 + seg * 8);
        }
#pragma unroll 5
        for (int i = tid; i < BN * 16; i += THREADS) {
            int row = i >> 4, seg = i & 15;
            pd_cp16(base + BM * ROWB + row * ROWB + seg * 16,
                    Bhi + (size_t)(n0 + row) * EMB + k0 + seg * 8);
        }
        pd_cp_commit();
    };

    load_stage(0);

    for (int s = 0; s < NSTG; s++) {
        if (s + 1 < NSTG) { load_stage(s + 1); pd_cp_wait(1); }
        else              pd_cp_wait(0);
        __syncthreads();

        const int buf = s & 1;
        const char* sa = sm + buf * BUFSZ;
        const char* sb = sm + buf * BUFSZ + BM * ROWB;

#pragma unroll
        for (int kk = 0; kk < 8; kk++) {
            uint32_t Ah[2][4], Bh[NFRAG][2];
#pragma unroll
            for (int i = 0; i < 2; i++) {
                uint32_t off = (uint32_t)((wm * 32 + i * 16 + r4) * ROWB + t * 4 + kk * 32);
                Ah[i][0] = *(const uint32_t*)(sa + off);
                Ah[i][1] = *(const uint32_t*)(sa + off + 8 * ROWB);
                Ah[i][2] = *(const uint32_t*)(sa + off + 16);
                Ah[i][3] = *(const uint32_t*)(sa + off + 8 * ROWB + 16);
            }
#pragma unroll
            for (int j = 0; j < NFRAG; j++) {
                uint32_t off = (uint32_t)((wn * WARP_N + j * 8 + r4) * ROWB + t * 4 + kk * 32);
                Bh[j][0] = *(const uint32_t*)(sb + off);
                Bh[j][1] = *(const uint32_t*)(sb + off + 16);
            }
#pragma unroll
            for (int i = 0; i < 2; i++)
#pragma unroll
                for (int j = 0; j < NFRAG; j++)
                    pd_mma_fp16(acc[i][j], Ah[i], Bh[j]);
        }
        __syncthreads();
    }

#pragma unroll
    for (int i = 0; i < 2; i++) {
        int row = m0 + wm * 32 + i * 16 + r4;
#pragma unroll
        for (int j = 0; j < NFRAG; j++) {
            int col = n0 + wn * WARP_N + j * 8 + t * 2;
            *(float2*)(C + (size_t)row * ldc + col)       = make_float2(acc[i][j][0], acc[i][j][1]);
            *(float2*)(C + (size_t)(row + 8) * ldc + col) = make_float2(acc[i][j][2], acc[i][j][3]);
        }
    }
}

// ---------------- fused window attention: TTILE=32, MUFU-free gelu --------
#define VSTRIDE 72       // halfs per val row (144 B)
#define PBSTRIDE 104     // halfs per PB row (208 B, 16B-multiple); 96 cols used

__global__ __launch_bounds__(512) void fused_kernel(
    const float* __restrict__ W_strain, const float* __restrict__ W_dmg,
    const float* __restrict__ b_dmg,    const float* __restrict__ W_bond,
    const float* __restrict__ W_dmg_out, const float* __restrict__ b_dmg_out)
{
    __shared__ __align__(16) __half s_vh[96 * VSTRIDE];    // 13.5 KB
    __shared__ __align__(16) __half s_vl[96 * VSTRIDE];    // 13.5 KB
    __shared__ float   s_disp[NROWS * BD];                 // 6.1 KB
    __shared__ float2  s_W2 [BD * 16];                     // 2 KB
    __shared__ __half2 s_PT [16 * NROWS];                  // 6.1 KB  [c][r]
    __shared__ __half2 s_ppT[16 * DELTA];                  // 4 KB    [c][j]
    __shared__ __align__(16) __half s_PBh[TTILE * PBSTRIDE]; // 6.5 KB
    __shared__ __align__(16) __half s_PBl[TTILE * PBSTRIDE]; // 6.5 KB
    __shared__ __half2 s_wout2[16];
    __shared__ float   s_inv[TTILE];

    const int b  = blockIdx.z;
    const int h  = blockIdx.y;
    const int t0 = blockIdx.x * TTILE;
    const int tid = threadIdx.x;
    const int base_s = t0 - (DELTA - 1);

    // ---- phase 0: loads + zero-init ----
    for (int i = tid; i < NROWS * (HS / 4); i += 512) {
        int r  = i >> 4;
        int c4 = (i & 15) * 4;
        int s  = base_s + r;
        float4 v = make_float4(0.f, 0.f, 0.f, 0.f);
        if (s >= 0)
            v = *(const float4*)(g_dv + (size_t)(b * SEQ + s) * NDV + 256 + h * HS + c4);
        uint32_t h01, l01, h23, l23;
        pd_split2h(v.x, v.y, h01, l01);
        pd_split2h(v.z, v.w, h23, l23);
        *(uint2*)(&s_vh[r * VSTRIDE + c4]) = make_uint2(h01, h23);
        *(uint2*)(&s_vl[r * VSTRIDE + c4]) = make_uint2(l01, l23);
    }
    if (tid < 32) {   // zero pad row 95 of val window
        *(uint32_t*)(&s_vh[95 * VSTRIDE + tid * 2]) = 0;
        *(uint32_t*)(&s_vl[95 * VSTRIDE + tid * 2]) = 0;
    }
    for (int i = tid; i < (TTILE * PBSTRIDE) / 2; i += 512) {
        *(uint32_t*)(&s_PBh[2 * i]) = 0;
        *(uint32_t*)(&s_PBl[2 * i]) = 0;
    }
    for (int i = tid; i < NROWS * (BD / 4); i += 512) {
        int r  = i >> 2;
        int c4 = (i & 3) * 4;
        int s  = base_s + r;
        float4 v = make_float4(0.f, 0.f, 0.f, 0.f);
        if (s >= 0)
            v = *(const float4*)(g_dv + (size_t)(b * SEQ + s) * NDV + h * BD + c4);
        *(float4*)(s_disp + r * BD + c4) = v;
    }
    if (tid < BD * 16)
        s_W2[tid] = make_float2(W_strain[tid], W_dmg[tid]);
    if (tid < 16)
        s_wout2[tid] = __floats2half2_rn(W_bond[tid], W_dmg_out[tid]);
    for (int i = tid; i < 16 * DELTA; i += 512) {
        int c = i >> 6, j = i & 63;
        s_ppT[i] = __floats2half2_rn(g_pos[j * BD + c], b_dmg[c]);
    }
    __syncthreads();

    // ---- phase 1: PT[c][r] = (disp_r . Ws_c, disp_r . Wd_c) as half2 ----
    for (int i = tid; i < NROWS * 16; i += 512) {
        int r = i >> 4, c = i & 15;
        u64 acc = 0;
#pragma unroll
        for (int k = 0; k < BD; k++)
            acc = pd_fma2(pd_dupf(s_disp[r * BD + k]), *(const u64*)(&s_W2[k * 16 + c]), acc);
        float sx, sy; pd_unpack2(acc, sx, sy);
        s_PT[c * NROWS + r] = __floats2half2_rn(sx, sy);
    }
    __syncthreads();

    // ---- phase 2: logits; each warp handles t rows wid and wid+16 ----
    const int wid  = tid >> 5;
    const int lane = tid & 31;

    // gelu(x) = x*(0.5 + x*(G1 + G2*x^2)); exact to <2e-5 for |x|<0.5
    const __half2 G1h = __float2half2_rn(0.3989423f);
    const __half2 G2h = __float2half2_rn(-0.0664904f);
    const __half2 H05 = __float2half2_rn(0.5f);
    const float c0  = 0.5f * b_dmg_out[0];
    const float L2E = 1.44269504089f, N5L2E = -7.21347520444f;

#pragma unroll
    for (int half_t = 0; half_t < 2; half_t++) {
        const int tt = wid + half_t * 16;
        const int t  = t0 + tt;

        __half2 accA = __float2half2_rn(0.f);
        __half2 accB = accA;

#pragma unroll
        for (int c = 0; c < 16; c++) {
            const __half2* Pc  = &s_PT[c * NROWS + tt];
            const __half2* ppc = &s_ppT[c * DELTA];
            const __half2 pre = Pc[DELTA - 1];
            const __half2 w2  = s_wout2[c];
            {
                __half2 xx = __hsub2(__hadd2(Pc[lane], ppc[lane]), pre);
                __half2 u  = __hmul2(xx, xx);
                __half2 p  = __hfma2(u, G2h, G1h);
                __half2 q  = __hfma2(xx, p, H05);
                __half2 m  = __hmul2(xx, q);
                accA = __hfma2(m, w2, accA);
            }
            {
                __half2 xx = __hsub2(__hadd2(Pc[lane + 32], ppc[lane + 32]), pre);
                __half2 u  = __hmul2(xx, xx);
                __half2 p  = __hfma2(u, G2h, G1h);
                __half2 q  = __hfma2(xx, p, H05);
                __half2 m  = __hmul2(xx, q);
                accB = __hfma2(m, w2, accB);
            }
        }

        const int jstart = (t < DELTA - 1) ? (DELTA - 1 - t) : 0;

        float p0, p1;
        {
            float bond = __low2float(accA), dm = __high2float(accA);
            float th2 = pd_tanhf(fmaf(dm, 0.5f, c0));
            float lt  = fmaf(th2, -5.f, bond);
            p0 = pd_ex2(fmaf(lt, L2E, N5L2E));
            if (lane < jstart) p0 = 0.f;
        }
        {
            float bond = __low2float(accB), dm = __high2float(accB);
            float th2 = pd_tanhf(fmaf(dm, 0.5f, c0));
            float lt  = fmaf(th2, -5.f, bond);
            p1 = pd_ex2(fmaf(lt, L2E, N5L2E));
            if (lane + 32 < jstart) p1 = 0.f;
        }

        {
            __half ph0 = __float2half_rn(p0);
            __half pl0 = __float2half_rn(p0 - __half2float(ph0));
            __half ph1 = __float2half_rn(p1);
            __half pl1 = __float2half_rn(p1 - __half2float(ph1));
            int bcol = tt * PBSTRIDE + tt + lane;
            s_PBh[bcol] = ph0;       s_PBl[bcol] = pl0;
            s_PBh[bcol + 32] = ph1;  s_PBl[bcol + 32] = pl1;
        }

        float ssum = p0 + p1;
#pragma unroll
        for (int off = 1; off < 32; off <<= 1)
            ssum += __shfl_xor_sync(0xffffffffu, ssum, off);
        if (lane == 0)
            s_inv[tt] = __fdividef(1.0f, ssum);
    }
    __syncthreads();

    // ---- phase 3: out[32][64] = PB[32][96] x val[96][64]; 16 warps ----
    {
        const int mhalf = wid >> 3;          // 0: t rows 0-15, 1: rows 16-31
        const int nb    = wid & 7;           // 8-col output block
        const int rowbase = mhalf * 16;
        float acc[4] = {0.f, 0.f, 0.f, 0.f};
        const uint32_t pbh = pd_smem_u32(s_PBh), pbl = pd_smem_u32(s_PBl);
        const uint32_t vhb = pd_smem_u32(s_vh),  vlb = pd_smem_u32(s_vl);
        const uint32_t rA = (uint32_t)(lane & 15);
        const uint32_t cA = (uint32_t)((lane >> 4) * 8);
#pragma unroll
        for (int kk = 0; kk < 5; kk++) {
            uint32_t offA = ((rowbase + rA) * PBSTRIDE + rowbase + kk * 16 + cA) * 2;
            uint32_t offB = ((rowbase + kk * 16 + (lane & 15)) * VSTRIDE + nb * 8) * 2;
            uint32_t Ah[4], Al[4], Bh[2], Bl[2];
            PD_LDSM_X4(Ah, pbh + offA);
            PD_LDSM_X4(Al, pbl + offA);
            PD_LDSM_X2T(Bh, vhb + offB);
            PD_LDSM_X2T(Bl, vlb + offB);
            pd_mma_fp16(acc, Ah, Bh);
            pd_mma_fp16(acc, Ah, Bl);
            pd_mma_fp16(acc, Al, Bh);
        }
        const int r0 = lane >> 2;
        const int e  = nb * 8 + (lane & 3) * 2;
        const float inv0 = s_inv[rowbase + r0], inv1 = s_inv[rowbase + r0 + 8];
        size_t ob0 = (size_t)(b * SEQ + t0 + rowbase + r0) * EMB + h * HS + e;
        *(__half2*)(&g_athi[ob0]) = __floats2half2_rn(acc[0] * inv0, acc[1] * inv0);
        size_t ob1 = ob0 + (size_t)8 * EMB;
        *(__half2*)(&g_athi[ob1]) = __floats2half2_rn(acc[2] * inv1, acc[3] * inv1);
    }
}

// ---------------- launch ----------------
extern "C" void kernel_launch(void* const* d_in, const int* in_sizes, int n_in,
                              void* d_out, int out_size)
{
    const float* x         = (const float*)d_in[0];
    const float* W_disp    = (const float*)d_in[1];
    const float* W_val     = (const float*)d_in[2];
    const float* rel       = (const float*)d_in[3];
    const float* W_strain  = (const float*)d_in[4];
    const float* W_pos     = (const float*)d_in[5];
    const float* W_bond    = (const float*)d_in[6];
    const float* W_dmg     = (const float*)d_in[7];
    const float* b_dmg     = (const float*)d_in[8];
    const float* W_dmg_out = (const float*)d_in[9];
    const float* b_dmg_out = (const float*)d_in[10];
    const float* W_cproj   = (const float*)d_in[11];
    float* out = (float*)d_out;

    float* dv_p;
    __half *xhi, *athi, *bthi, *cthi;
    cudaGetSymbolAddress((void**)&dv_p, g_dv);
    cudaGetSymbolAddress((void**)&xhi, g_xhi);
    cudaGetSymbolAddress((void**)&athi, g_athi);
    cudaGetSymbolAddress((void**)&bthi, g_bthi);
    cudaGetSymbolAddress((void**)&cthi, g_cthi);

    const int SMEM_DV = (128 + 160) * ROWB * 2;   // 156672
    const int SMEM_CP = (128 + 128) * ROWB * 2;   // 139264
    cudaFuncSetAttribute((const void*)gemm_kernel<128, 160, 512, 4>,
                         cudaFuncAttributeMaxDynamicSharedMemorySize, SMEM_DV);
    cudaFuncSetAttribute((const void*)gemm_kernel<128, 128, 512, 4>,
                         cudaFuncAttributeMaxDynamicSharedMemorySize, SMEM_CP);

    split_x_kernel<<<(MTOT * EMB / 4) / 512, 512>>>(x);
    splitT_kernel<<<dim3(2304 / 32, EMB / 32), dim3(32, 8)>>>(W_disp, W_val, W_cproj, rel, W_pos);

    gemm_kernel<128, 160, 512, 4><<<dim3(NDV / 160, MTOT / 128), 512, SMEM_DV>>>(
        xhi, bthi, dv_p, NDV);
    fused_kernel<<<dim3(SEQ / TTILE, NH, BATCH), 512>>>(W_strain, W_dmg, b_dmg,
                                                        W_bond, W_dmg_out, b_dmg_out);
    gemm_kernel<128, 128, 512, 4><<<dim3(EMB / 128, MTOT / 128), 512, SMEM_CP>>>(
        athi, cthi, out, EMB);
}

// round 15
// speedup vs baseline: 1.0878x; 1.0878x over previous
#include <cuda_runtime.h>
#include <cuda_fp16.h>
#include <cstdint>
#include <math.h>

#define BATCH 2
#define SEQ   1024
#define EMB   1024
#define NH    16
#define HS    64
#define BD    16
#define DELTA 64
#define TTILE 32
#define NROWS (TTILE + DELTA - 1)   // 95
#define MTOT  (BATCH * SEQ)         // 2048
#define NDV   1280                  // disp (256) ++ val (1024) columns

// ---------------- scratch (static device memory; no allocs) ----------------
__device__ float g_dv [MTOT * NDV];                // [disp | val] fp32
__device__ float g_pos[DELTA * BD];
__device__ __half g_xhi [MTOT * EMB];
__device__ __half g_athi[MTOT * EMB];
__device__ __half g_bthi[NDV * EMB];               // [W_disp^T ++ W_val^T]
__device__ __half g_cthi[EMB * EMB];               // W_cproj^T

// ---------------- helpers (pd_ prefix: no vendor-header collisions) --------
typedef unsigned long long u64;

__device__ __forceinline__ u64 pd_dupf(float v) {
    u64 r; asm("mov.b64 %0, {%1, %1};" : "=l"(r) : "f"(v)); return r;
}
__device__ __forceinline__ void pd_unpack2(u64 v, float& a, float& b) {
    asm("mov.b64 {%0, %1}, %2;" : "=f"(a), "=f"(b) : "l"(v));
}
__device__ __forceinline__ u64 pd_fma2(u64 a, u64 b, u64 c) {
    u64 r; asm("fma.rn.f32x2 %0, %1, %2, %3;" : "=l"(r) : "l"(a), "l"(b), "l"(c)); return r;
}
__device__ __forceinline__ float pd_tanhf(float x) {
    float r; asm("tanh.approx.f32 %0, %1;" : "=f"(r) : "f"(x)); return r;
}
__device__ __forceinline__ float pd_ex2(float x) {
    float r; asm("ex2.approx.f32 %0, %1;" : "=f"(r) : "f"(x)); return r;
}
__device__ __forceinline__ uint32_t pd_smem_u32(const void* p) {
    uint32_t a;
    asm("{ .reg .u64 t; cvta.to.shared.u64 t, %1; cvt.u32.u64 %0, t; }" : "=r"(a) : "l"(p));
    return a;
}
__device__ __forceinline__ void pd_cp16(uint32_t dst, const void* src) {
    asm volatile("{ .reg .u64 g; cvta.to.global.u64 g, %1; cp.async.cg.shared.global [%0], [g], 16; }"
                 :: "r"(dst), "l"(src) : "memory");
}
__device__ __forceinline__ void pd_cp_commit() { asm volatile("cp.async.commit_group;" ::: "memory"); }
__device__ __forceinline__ void pd_cp_wait(int pending) {
    if (pending) asm volatile("cp.async.wait_group 1;" ::: "memory");
    else         asm volatile("cp.async.wait_group 0;" ::: "memory");
}

__device__ __forceinline__ void pd_split2h(float a, float b, uint32_t& hi, uint32_t& lo) {
    __half2 h2 = __floats2half2_rn(a, b);
    float ra = a - __half2float(h2.x);
    float rb = b - __half2float(h2.y);
    __half2 l2 = __floats2half2_rn(ra, rb);
    hi = *reinterpret_cast<uint32_t*>(&h2);
    lo = *reinterpret_cast<uint32_t*>(&l2);
}

__device__ __forceinline__ void pd_mma_fp16(float* c, const uint32_t* a, const uint32_t* b) {
    asm volatile(
        "mma.sync.aligned.m16n8k16.row.col.f32.f16.f16.f32 "
        "{%0,%1,%2,%3}, {%4,%5,%6,%7}, {%8,%9}, {%0,%1,%2,%3};"
        : "+f"(c[0]), "+f"(c[1]), "+f"(c[2]), "+f"(c[3])
        : "r"(a[0]), "r"(a[1]), "r"(a[2]), "r"(a[3]), "r"(b[0]), "r"(b[1]));
}

#define PD_LDSM_X4(r, a) \
    asm volatile("ldmatrix.sync.aligned.m8n8.x4.shared.b16 {%0,%1,%2,%3}, [%4];" \
                 : "=r"((r)[0]), "=r"((r)[1]), "=r"((r)[2]), "=r"((r)[3]) : "r"(a))
#define PD_LDSM_X2T(r, a) \
    asm volatile("ldmatrix.sync.aligned.m8n8.x2.trans.shared.b16 {%0,%1}, [%2];" \
                 : "=r"((r)[0]), "=r"((r)[1]) : "r"(a))

// ---------------- conversion kernels ----------------
__global__ __launch_bounds__(512) void split_x_kernel(const float* __restrict__ x) {
    size_t i = (size_t)blockIdx.x * 512 + threadIdx.x;   // over 512K float4
    float4 v = ((const float4*)x)[i];
    __half2 a = __floats2half2_rn(v.x, v.y);
    __half2 b = __floats2half2_rn(v.z, v.w);
    ((__half2*)g_xhi)[2 * i]     = a;
    ((__half2*)g_xhi)[2 * i + 1] = b;
}

// transpose+convert; block (0,0) also computes pos = rel_pos_emb @ W_pos.
__global__ void splitT_kernel(const float* __restrict__ Wd,
                              const float* __restrict__ Wv,
                              const float* __restrict__ Wc,
                              const float* __restrict__ rel,
                              const float* __restrict__ Wp)
{
    __shared__ float tile[32][33];
    const int k0 = blockIdx.y * 32;
    const int n0 = blockIdx.x * 32;
    const int tx = threadIdx.x, ty = threadIdx.y;   // 32 x 8
    const int tid = ty * 32 + tx;

    if (blockIdx.x == 0 && blockIdx.y == 0) {
#pragma unroll
        for (int q = 0; q < 4; q++) {
            int i = tid + q * 256;     // over 1024 outputs
            int j = i >> 4, c = i & 15;
            float s = 0.f;
#pragma unroll
            for (int k = 0; k < BD; k++)
                s = fmaf(rel[j * BD + k], Wp[k * BD + c], s);
            g_pos[i] = s;
        }
    }

#pragma unroll
    for (int q = 0; q < 4; q++) {
        int k = k0 + ty + 8 * q;
        int n = n0 + tx;
        float v;
        if (n < 256)        v = Wd[(size_t)k * 256 + n];
        else if (n < 1280)  v = Wv[(size_t)k * EMB + (n - 256)];
        else                v = Wc[(size_t)k * EMB + (n - 1280)];
        tile[ty + 8 * q][tx] = v;
    }
    __syncthreads();
#pragma unroll
    for (int q = 0; q < 4; q++) {
        int n = n0 + ty + 8 * q;
        int k = k0 + tx;
        __half hv = __float2half_rn(tile[tx][ty + 8 * q]);
        if (n < 1280) g_bthi[(size_t)n * EMB + k] = hv;
        else          g_cthi[(size_t)(n - 1280) * EMB + k] = hv;
    }
}

// ---------------- fp16 HMMA GEMM: K-chunk 128, double buffered ----------------
#define ROWB 272        // 128 halfs (256 B) + 16 B pad; 68 words ≡ 4 mod 32: conflict-free
#define KCH  128
#define NSTG (EMB / KCH)   // 8

template<int BM, int BN, int THREADS, int WN>
__global__ __launch_bounds__(THREADS) void gemm_kernel(
    const __half* __restrict__ Ahi, const __half* __restrict__ Bhi,
    float* __restrict__ C, int ldc)
{
    extern __shared__ __align__(16) char sm[];
    const uint32_t sbase = pd_smem_u32(sm);
    const int tid  = threadIdx.x;
    const int wid  = tid >> 5;
    const int lane = tid & 31;
    const int wm   = wid / WN;
    const int wn   = wid % WN;
    const int m0 = blockIdx.y * BM;
    const int n0 = blockIdx.x * BN;
    const int r4 = lane >> 2;
    const int t  = lane & 3;

    constexpr int WARP_N = BN / WN;        // 32 or 40
    constexpr int NFRAG  = WARP_N / 8;     // 4 or 5
    const int BUFSZ = (BM + BN) * ROWB;

    float acc[2][NFRAG][4];
#pragma unroll
    for (int i = 0; i < 2; i++)
#pragma unroll
        for (int j = 0; j < NFRAG; j++)
#pragma unroll
            for (int q = 0; q < 4; q++) acc[i][j][q] = 0.f;

    auto load_stage = [&](int s) {
        const int buf = s & 1;
        const int k0 = s * KCH;
        uint32_t base = sbase + buf * BUFSZ;
#pragma unroll 4
        for (int i = tid; i < BM * 16; i += THREADS) {
            int row = i >> 4, seg = i & 15;
            pd_cp16(base + row * ROWB + seg * 16,
                    Ahi + (size_t)(m0 + row) * EMB + k0 + seg * 8);
        }
#pragma unroll 5
        for (int i = tid; i < BN * 16; i += THREADS) {
            int row = i >> 4, seg = i & 15;
            pd_cp16(base + BM * ROWB + row * ROWB + seg * 16,
                    Bhi + (size_t)(n0 + row) * EMB + k0 + seg * 8);
        }
        pd_cp_commit();
    };

    load_stage(0);

    for (int s = 0; s < NSTG; s++) {
        if (s + 1 < NSTG) { load_stage(s + 1); pd_cp_wait(1); }
        else              pd_cp_wait(0);
        __syncthreads();

        const int buf = s & 1;
        const char* sa = sm + buf * BUFSZ;
        const char* sb = sm + buf * BUFSZ + BM * ROWB;

#pragma unroll
        for (int kk = 0; kk < 8; kk++) {
            uint32_t Ah[2][4], Bh[NFRAG][2];
#pragma unroll
            for (int i = 0; i < 2; i++) {
                uint32_t off = (uint32_t)((wm * 32 + i * 16 + r4) * ROWB + t * 4 + kk * 32);
                Ah[i][0] = *(const uint32_t*)(sa + off);
                Ah[i][1] = *(const uint32_t*)(sa + off + 8 * ROWB);
                Ah[i][2] = *(const uint32_t*)(sa + off + 16);
                Ah[i][3] = *(const uint32_t*)(sa + off + 8 * ROWB + 16);
            }
#pragma unroll
            for (int j = 0; j < NFRAG; j++) {
                uint32_t off = (uint32_t)((wn * WARP_N + j * 8 + r4) * ROWB + t * 4 + kk * 32);
                Bh[j][0] = *(const uint32_t*)(sb + off);
                Bh[j][1] = *(const uint32_t*)(sb + off + 16);
            }
#pragma unroll
            for (int i = 0; i < 2; i++)
#pragma unroll
                for (int j = 0; j < NFRAG; j++)
                    pd_mma_fp16(acc[i][j], Ah[i], Bh[j]);
        }
        __syncthreads();
    }

#pragma unroll
    for (int i = 0; i < 2; i++) {
        int row = m0 + wm * 32 + i * 16 + r4;
#pragma unroll
        for (int j = 0; j < NFRAG; j++) {
            int col = n0 + wn * WARP_N + j * 8 + t * 2;
            *(float2*)(C + (size_t)row * ldc + col)       = make_float2(acc[i][j][0], acc[i][j][1]);
            *(float2*)(C + (size_t)(row + 8) * ldc + col) = make_float2(acc[i][j][2], acc[i][j][3]);
        }
    }
}

// ---------------- fused window attention: TTILE=32, 2 CTAs/SM forced -------
#define VSTRIDE 72       // halfs per val row (144 B)
#define PBSTRIDE 104     // halfs per PB row (208 B, 16B-multiple); 96 cols used

__global__ __launch_bounds__(512, 2) void fused_kernel(
    const float* __restrict__ W_strain, const float* __restrict__ W_dmg,
    const float* __restrict__ b_dmg,    const float* __restrict__ W_bond,
    const float* __restrict__ W_dmg_out, const float* __restrict__ b_dmg_out)
{
    __shared__ __align__(16) __half s_vh[96 * VSTRIDE];    // 13.5 KB
    __shared__ __align__(16) __half s_vl[96 * VSTRIDE];    // 13.5 KB
    __shared__ float   s_disp[NROWS * BD];                 // 6.1 KB
    __shared__ float2  s_W2 [BD * 16];                     // 2 KB
    __shared__ __half2 s_PT [16 * NROWS];                  // 6.1 KB  [c][r]
    __shared__ __half2 s_ppT[16 * DELTA];                  // 4 KB    [c][j]
    __shared__ __align__(16) __half s_PBh[TTILE * PBSTRIDE]; // 6.5 KB
    __shared__ __align__(16) __half s_PBl[TTILE * PBSTRIDE]; // 6.5 KB
    __shared__ __half2 s_wout2[16];
    __shared__ float   s_inv[TTILE];

    const int b  = blockIdx.z;
    const int h  = blockIdx.y;
    const int t0 = blockIdx.x * TTILE;
    const int tid = threadIdx.x;
    const int base_s = t0 - (DELTA - 1);

    // ---- phase 0: loads + zero-init ----
    for (int i = tid; i < NROWS * (HS / 4); i += 512) {
        int r  = i >> 4;
        int c4 = (i & 15) * 4;
        int s  = base_s + r;
        float4 v = make_float4(0.f, 0.f, 0.f, 0.f);
        if (s >= 0)
            v = *(const float4*)(g_dv + (size_t)(b * SEQ + s) * NDV + 256 + h * HS + c4);
        uint32_t h01, l01, h23, l23;
        pd_split2h(v.x, v.y, h01, l01);
        pd_split2h(v.z, v.w, h23, l23);
        *(uint2*)(&s_vh[r * VSTRIDE + c4]) = make_uint2(h01, h23);
        *(uint2*)(&s_vl[r * VSTRIDE + c4]) = make_uint2(l01, l23);
    }
    if (tid < 32) {   // zero pad row 95 of val window
        *(uint32_t*)(&s_vh[95 * VSTRIDE + tid * 2]) = 0;
        *(uint32_t*)(&s_vl[95 * VSTRIDE + tid * 2]) = 0;
    }
    for (int i = tid; i < (TTILE * PBSTRIDE) / 2; i += 512) {
        *(uint32_t*)(&s_PBh[2 * i]) = 0;
        *(uint32_t*)(&s_PBl[2 * i]) = 0;
    }
    for (int i = tid; i < NROWS * (BD / 4); i += 512) {
        int r  = i >> 2;
        int c4 = (i & 3) * 4;
        int s  = base_s + r;
        float4 v = make_float4(0.f, 0.f, 0.f, 0.f);
        if (s >= 0)
            v = *(const float4*)(g_dv + (size_t)(b * SEQ + s) * NDV + h * BD + c4);
        *(float4*)(s_disp + r * BD + c4) = v;
    }
    if (tid < BD * 16)
        s_W2[tid] = make_float2(W_strain[tid], W_dmg[tid]);
    if (tid < 16)
        s_wout2[tid] = __floats2half2_rn(W_bond[tid], W_dmg_out[tid]);
    for (int i = tid; i < 16 * DELTA; i += 512) {
        int c = i >> 6, j = i & 63;
        s_ppT[i] = __floats2half2_rn(g_pos[j * BD + c], b_dmg[c]);
    }
    __syncthreads();

    // ---- phase 1: PT[c][r] = (disp_r . Ws_c, disp_r . Wd_c) as half2 ----
    for (int i = tid; i < NROWS * 16; i += 512) {
        int r = i >> 4, c = i & 15;
        u64 acc = 0;
#pragma unroll
        for (int k = 0; k < BD; k++)
            acc = pd_fma2(pd_dupf(s_disp[r * BD + k]), *(const u64*)(&s_W2[k * 16 + c]), acc);
        float sx, sy; pd_unpack2(acc, sx, sy);
        s_PT[c * NROWS + r] = __floats2half2_rn(sx, sy);
    }
    __syncthreads();

    // ---- phase 2: logits; each warp handles t rows wid and wid+16 ----
    const int wid  = tid >> 5;
    const int lane = tid & 31;

    // gelu(x) = x*(0.5 + x*(G1 + G2*x^2)); exact to <2e-5 for |x|<0.5
    const __half2 G1h = __float2half2_rn(0.3989423f);
    const __half2 G2h = __float2half2_rn(-0.0664904f);
    const __half2 H05 = __float2half2_rn(0.5f);
    const float c0  = 0.5f * b_dmg_out[0];
    const float L2E = 1.44269504089f, N5L2E = -7.21347520444f;

#pragma unroll
    for (int half_t = 0; half_t < 2; half_t++) {
        const int tt = wid + half_t * 16;
        const int t  = t0 + tt;

        __half2 accA = __float2half2_rn(0.f);
        __half2 accB = accA;

#pragma unroll
        for (int c = 0; c < 16; c++) {
            const __half2* Pc  = &s_PT[c * NROWS + tt];
            const __half2* ppc = &s_ppT[c * DELTA];
            const __half2 pre = Pc[DELTA - 1];
            const __half2 w2  = s_wout2[c];
            {
                __half2 xx = __hsub2(__hadd2(Pc[lane], ppc[lane]), pre);
                __half2 u  = __hmul2(xx, xx);
                __half2 p  = __hfma2(u, G2h, G1h);
                __half2 q  = __hfma2(xx, p, H05);
                __half2 m  = __hmul2(xx, q);
                accA = __hfma2(m, w2, accA);
            }
            {
                __half2 xx = __hsub2(__hadd2(Pc[lane + 32], ppc[lane + 32]), pre);
                __half2 u  = __hmul2(xx, xx);
                __half2 p  = __hfma2(u, G2h, G1h);
                __half2 q  = __hfma2(xx, p, H05);
                __half2 m  = __hmul2(xx, q);
                accB = __hfma2(m, w2, accB);
            }
        }

        const int jstart = (t < DELTA - 1) ? (DELTA - 1 - t) : 0;

        float p0, p1;
        {
            float bond = __low2float(accA), dm = __high2float(accA);
            float th2 = pd_tanhf(fmaf(dm, 0.5f, c0));
            float lt  = fmaf(th2, -5.f, bond);
            p0 = pd_ex2(fmaf(lt, L2E, N5L2E));
            if (lane < jstart) p0 = 0.f;
        }
        {
            float bond = __low2float(accB), dm = __high2float(accB);
            float th2 = pd_tanhf(fmaf(dm, 0.5f, c0));
            float lt  = fmaf(th2, -5.f, bond);
            p1 = pd_ex2(fmaf(lt, L2E, N5L2E));
            if (lane + 32 < jstart) p1 = 0.f;
        }

        {
            __half ph0 = __float2half_rn(p0);
            __half pl0 = __float2half_rn(p0 - __half2float(ph0));
            __half ph1 = __float2half_rn(p1);
            __half pl1 = __float2half_rn(p1 - __half2float(ph1));
            int bcol = tt * PBSTRIDE + tt + lane;
            s_PBh[bcol] = ph0;       s_PBl[bcol] = pl0;
            s_PBh[bcol + 32] = ph1;  s_PBl[bcol + 32] = pl1;
        }

        float ssum = p0 + p1;
#pragma unroll
        for (int off = 1; off < 32; off <<= 1)
            ssum += __shfl_xor_sync(0xffffffffu, ssum, off);
        if (lane == 0)
            s_inv[tt] = __fdividef(1.0f, ssum);
    }
    __syncthreads();

    // ---- phase 3: out[32][64] = PB[32][96] x val[96][64]; 16 warps ----
    {
        const int mhalf = wid >> 3;          // 0: t rows 0-15, 1: rows 16-31
        const int nb    = wid & 7;           // 8-col output block
        const int rowbase = mhalf * 16;
        float acc[4] = {0.f, 0.f, 0.f, 0.f};
        const uint32_t pbh = pd_smem_u32(s_PBh), pbl = pd_smem_u32(s_PBl);
        const uint32_t vhb = pd_smem_u32(s_vh),  vlb = pd_smem_u32(s_vl);
        const uint32_t rA = (uint32_t)(lane & 15);
        const uint32_t cA = (uint32_t)((lane >> 4) * 8);
#pragma unroll
        for (int kk = 0; kk < 5; kk++) {
            uint32_t offA = ((rowbase + rA) * PBSTRIDE + rowbase + kk * 16 + cA) * 2;
            uint32_t offB = ((rowbase + kk * 16 + (lane & 15)) * VSTRIDE + nb * 8) * 2;
            uint32_t Ah[4], Al[4], Bh[2], Bl[2];
            PD_LDSM_X4(Ah, pbh + offA);
            PD_LDSM_X4(Al, pbl + offA);
            PD_LDSM_X2T(Bh, vhb + offB);
            PD_LDSM_X2T(Bl, vlb + offB);
            pd_mma_fp16(acc, Ah, Bh);
            pd_mma_fp16(acc, Ah, Bl);
            pd_mma_fp16(acc, Al, Bh);
        }
        const int r0 = lane >> 2;
        const int e  = nb * 8 + (lane & 3) * 2;
        const float inv0 = s_inv[rowbase + r0], inv1 = s_inv[rowbase + r0 + 8];
        size_t ob0 = (size_t)(b * SEQ + t0 + rowbase + r0) * EMB + h * HS + e;
        *(__half2*)(&g_athi[ob0]) = __floats2half2_rn(acc[0] * inv0, acc[1] * inv0);
        size_t ob1 = ob0 + (size_t)8 * EMB;
        *(__half2*)(&g_athi[ob1]) = __floats2half2_rn(acc[2] * inv1, acc[3] * inv1);
    }
}

// ---------------- launch ----------------
extern "C" void kernel_launch(void* const* d_in, const int* in_sizes, int n_in,
                              void* d_out, int out_size)
{
    const float* x         = (const float*)d_in[0];
    const float* W_disp    = (const float*)d_in[1];
    const float* W_val     = (const float*)d_in[2];
    const float* rel       = (const float*)d_in[3];
    const float* W_strain  = (const float*)d_in[4];
    const float* W_pos     = (const float*)d_in[5];
    const float* W_bond    = (const float*)d_in[6];
    const float* W_dmg     = (const float*)d_in[7];
    const float* b_dmg     = (const float*)d_in[8];
    const float* W_dmg_out = (const float*)d_in[9];
    const float* b_dmg_out = (const float*)d_in[10];
    const float* W_cproj   = (const float*)d_in[11];
    float* out = (float*)d_out;

    float* dv_p;
    __half *xhi, *athi, *bthi, *cthi;
    cudaGetSymbolAddress((void**)&dv_p, g_dv);
    cudaGetSymbolAddress((void**)&xhi, g_xhi);
    cudaGetSymbolAddress((void**)&athi, g_athi);
    cudaGetSymbolAddress((void**)&bthi, g_bthi);
    cudaGetSymbolAddress((void**)&cthi, g_cthi);

    const int SMEM_DV = (128 + 160) * ROWB * 2;   // 156672
    const int SMEM_CP = (128 + 128) * ROWB * 2;   // 139264
    cudaFuncSetAttribute((const void*)gemm_kernel<128, 160, 512, 4>,
                         cudaFuncAttributeMaxDynamicSharedMemorySize, SMEM_DV);
    cudaFuncSetAttribute((const void*)gemm_kernel<128, 128, 512, 4>,
                         cudaFuncAttributeMaxDynamicSharedMemorySize, SMEM_CP);

    split_x_kernel<<<(MTOT * EMB / 4) / 512, 512>>>(x);
    splitT_kernel<<<dim3(2304 / 32, EMB / 32), dim3(32, 8)>>>(W_disp, W_val, W_cproj, rel, W_pos);

    gemm_kernel<128, 160, 512, 4><<<dim3(NDV / 160, MTOT / 128), 512, SMEM_DV>>>(
        xhi, bthi, dv_p, NDV);
    fused_kernel<<<dim3(SEQ / TTILE, NH, BATCH), 512>>>(W_strain, W_dmg, b_dmg,
                                                        W_bond, W_dmg_out, b_dmg_out);
    gemm_kernel<128, 128, 512, 4><<<dim3(EMB / 128, MTOT / 128), 512, SMEM_CP>>>(
        athi, cthi, out, EMB);
}

// round 17
// speedup vs baseline: 1.1216x; 1.0311x over previous
#include <cuda_runtime.h>
#include <cuda_fp16.h>
#include <cstdint>
#include <math.h>

#define BATCH 2
#define SEQ   1024
#define EMB   1024
#define NH    16
#define HS    64
#define BD    16
#define DELTA 64
#define TTILE 32
#define NROWS (TTILE + DELTA - 1)   // 95
#define MTOT  (BATCH * SEQ)         // 2048
#define NDV   1280                  // disp (256) ++ val (1024) columns

// ---------------- scratch (static device memory; no allocs) ----------------
__device__ float g_dv [MTOT * NDV];                // [disp | val] fp32
__device__ float g_pos[DELTA * BD];
__device__ __half g_xhi [MTOT * EMB];
__device__ __half g_athi[MTOT * EMB];
__device__ __half g_bthi[NDV * EMB];               // [W_disp^T ++ W_val^T]
__device__ __half g_cthi[EMB * EMB];               // W_cproj^T

// ---------------- helpers (pd_ prefix: no vendor-header collisions) --------
typedef unsigned long long u64;

__device__ __forceinline__ u64 pd_dupf(float v) {
    u64 r; asm("mov.b64 %0, {%1, %1};" : "=l"(r) : "f"(v)); return r;
}
__device__ __forceinline__ void pd_unpack2(u64 v, float& a, float& b) {
    asm("mov.b64 {%0, %1}, %2;" : "=f"(a), "=f"(b) : "l"(v));
}
__device__ __forceinline__ u64 pd_fma2(u64 a, u64 b, u64 c) {
    u64 r; asm("fma.rn.f32x2 %0, %1, %2, %3;" : "=l"(r) : "l"(a), "l"(b), "l"(c)); return r;
}
__device__ __forceinline__ float pd_tanhf(float x) {
    float r; asm("tanh.approx.f32 %0, %1;" : "=f"(r) : "f"(x)); return r;
}
__device__ __forceinline__ float pd_ex2(float x) {
    float r; asm("ex2.approx.f32 %0, %1;" : "=f"(r) : "f"(x)); return r;
}
__device__ __forceinline__ uint32_t pd_smem_u32(const void* p) {
    uint32_t a;
    asm("{ .reg .u64 t; cvta.to.shared.u64 t, %1; cvt.u32.u64 %0, t; }" : "=r"(a) : "l"(p));
    return a;
}
__device__ __forceinline__ void pd_cp16(uint32_t dst, const void* src) {
    asm volatile("{ .reg .u64 g; cvta.to.global.u64 g, %1; cp.async.cg.shared.global [%0], [g], 16; }"
                 :: "r"(dst), "l"(src) : "memory");
}
__device__ __forceinline__ void pd_cp_commit() { asm volatile("cp.async.commit_group;" ::: "memory"); }
__device__ __forceinline__ void pd_cp_wait(int pending) {
    if (pending) asm volatile("cp.async.wait_group 1;" ::: "memory");
    else         asm volatile("cp.async.wait_group 0;" ::: "memory");
}

__device__ __forceinline__ void pd_mma_fp16(float* c, const uint32_t* a, const uint32_t* b) {
    asm volatile(
        "mma.sync.aligned.m16n8k16.row.col.f32.f16.f16.f32 "
        "{%0,%1,%2,%3}, {%4,%5,%6,%7}, {%8,%9}, {%0,%1,%2,%3};"
        : "+f"(c[0]), "+f"(c[1]), "+f"(c[2]), "+f"(c[3])
        : "r"(a[0]), "r"(a[1]), "r"(a[2]), "r"(a[3]), "r"(b[0]), "r"(b[1]));
}

#define PD_LDSM_X4(r, a) \
    asm volatile("ldmatrix.sync.aligned.m8n8.x4.shared.b16 {%0,%1,%2,%3}, [%4];" \
                 : "=r"((r)[0]), "=r"((r)[1]), "=r"((r)[2]), "=r"((r)[3]) : "r"(a))
#define PD_LDSM_X2T(r, a) \
    asm volatile("ldmatrix.sync.aligned.m8n8.x2.trans.shared.b16 {%0,%1}, [%2];" \
                 : "=r"((r)[0]), "=r"((r)[1]) : "r"(a))

// ---------------- conversion kernels ----------------
__global__ __launch_bounds__(512) void split_x_kernel(const float* __restrict__ x) {
    size_t i = (size_t)blockIdx.x * 512 + threadIdx.x;   // over 512K float4
    float4 v = ((const float4*)x)[i];
    __half2 a = __floats2half2_rn(v.x, v.y);
    __half2 b = __floats2half2_rn(v.z, v.w);
    ((__half2*)g_xhi)[2 * i]     = a;
    ((__half2*)g_xhi)[2 * i + 1] = b;
}

// transpose+convert; block (0,0) also computes pos = rel_pos_emb @ W_pos.
__global__ void splitT_kernel(const float* __restrict__ Wd,
                              const float* __restrict__ Wv,
                              const float* __restrict__ Wc,
                              const float* __restrict__ rel,
                              const float* __restrict__ Wp)
{
    __shared__ float tile[32][33];
    const int k0 = blockIdx.y * 32;
    const int n0 = blockIdx.x * 32;
    const int tx = threadIdx.x, ty = threadIdx.y;   // 32 x 8
    const int tid = ty * 32 + tx;

    if (blockIdx.x == 0 && blockIdx.y == 0) {
#pragma unroll
        for (int q = 0; q < 4; q++) {
            int i = tid + q * 256;     // over 1024 outputs
            int j = i >> 4, c = i & 15;
            float s = 0.f;
#pragma unroll
            for (int k = 0; k < BD; k++)
                s = fmaf(rel[j * BD + k], Wp[k * BD + c], s);
            g_pos[i] = s;
        }
    }

#pragma unroll
    for (int q = 0; q < 4; q++) {
        int k = k0 + ty + 8 * q;
        int n = n0 + tx;
        float v;
        if (n < 256)        v = Wd[(size_t)k * 256 + n];
        else if (n < 1280)  v = Wv[(size_t)k * EMB + (n - 256)];
        else                v = Wc[(size_t)k * EMB + (n - 1280)];
        tile[ty + 8 * q][tx] = v;
    }
    __syncthreads();
#pragma unroll
    for (int q = 0; q < 4; q++) {
        int n = n0 + ty + 8 * q;
        int k = k0 + tx;
        __half hv = __float2half_rn(tile[tx][ty + 8 * q]);
        if (n < 1280) g_bthi[(size_t)n * EMB + k] = hv;
        else          g_cthi[(size_t)(n - 1280) * EMB + k] = hv;
    }
}

// ---------------- fp16 HMMA GEMM: K-chunk 128, double buffered ----------------
#define ROWB 272        // 128 halfs (256 B) + 16 B pad; 68 words ≡ 4 mod 32: conflict-free
#define KCH  128
#define NSTG (EMB / KCH)   // 8

template<int BM, int BN, int THREADS, int WN>
__global__ __launch_bounds__(THREADS) void gemm_kernel(
    const __half* __restrict__ Ahi, const __half* __restrict__ Bhi,
    float* __restrict__ C, int ldc)
{
    extern __shared__ __align__(16) char sm[];
    const uint32_t sbase = pd_smem_u32(sm);
    const int tid  = threadIdx.x;
    const int wid  = tid >> 5;
    const int lane = tid & 31;
    const int wm   = wid / WN;
    const int wn   = wid % WN;
    const int m0 = blockIdx.y * BM;
    const int n0 = blockIdx.x * BN;
    const int r4 = lane >> 2;
    const int t  = lane & 3;

    constexpr int WARP_N = BN / WN;        // 32 or 40
    constexpr int NFRAG  = WARP_N / 8;     // 4 or 5
    const int BUFSZ = (BM + BN) * ROWB;

    float acc[2][NFRAG][4];
#pragma unroll
    for (int i = 0; i < 2; i++)
#pragma unroll
        for (int j = 0; j < NFRAG; j++)
#pragma unroll
            for (int q = 0; q < 4; q++) acc[i][j][q] = 0.f;

    auto load_stage = [&](int s) {
        const int buf = s & 1;
        const int k0 = s * KCH;
        uint32_t base = sbase + buf * BUFSZ;
#pragma unroll 4
        for (int i = tid; i < BM * 16; i += THREADS) {
            int row = i >> 4, seg = i & 15;
            pd_cp16(base + row * ROWB + seg * 16,
                    Ahi + (size_t)(m0 + row) * EMB + k0 + seg * 8);
        }
#pragma unroll 5
        for (int i = tid; i < BN * 16; i += THREADS) {
            int row = i >> 4, seg = i & 15;
            pd_cp16(base + BM * ROWB + row * ROWB + seg * 16,
                    Bhi + (size_t)(n0 + row) * EMB + k0 + seg * 8);
        }
        pd_cp_commit();
    };

    load_stage(0);

    for (int s = 0; s < NSTG; s++) {
        if (s + 1 < NSTG) { load_stage(s + 1); pd_cp_wait(1); }
        else              pd_cp_wait(0);
        __syncthreads();

        const int buf = s & 1;
        const char* sa = sm + buf * BUFSZ;
        const char* sb = sm + buf * BUFSZ + BM * ROWB;

#pragma unroll
        for (int kk = 0; kk < 8; kk++) {
            uint32_t Ah[2][4], Bh[NFRAG][2];
#pragma unroll
            for (int i = 0; i < 2; i++) {
                uint32_t off = (uint32_t)((wm * 32 + i * 16 + r4) * ROWB + t * 4 + kk * 32);
                Ah[i][0] = *(const uint32_t*)(sa + off);
                Ah[i][1] = *(const uint32_t*)(sa + off + 8 * ROWB);
                Ah[i][2] = *(const uint32_t*)(sa + off + 16);
                Ah[i][3] = *(const uint32_t*)(sa + off + 8 * ROWB + 16);
            }
#pragma unroll
            for (int j = 0; j < NFRAG; j++) {
                uint32_t off = (uint32_t)((wn * WARP_N + j * 8 + r4) * ROWB + t * 4 + kk * 32);
                Bh[j][0] = *(const uint32_t*)(sb + off);
                Bh[j][1] = *(const uint32_t*)(sb + off + 16);
            }
#pragma unroll
            for (int i = 0; i < 2; i++)
#pragma unroll
                for (int j = 0; j < NFRAG; j++)
                    pd_mma_fp16(acc[i][j], Ah[i], Bh[j]);
        }
        __syncthreads();
    }

#pragma unroll
    for (int i = 0; i < 2; i++) {
        int row = m0 + wm * 32 + i * 16 + r4;
#pragma unroll
        for (int j = 0; j < NFRAG; j++) {
            int col = n0 + wn * WARP_N + j * 8 + t * 2;
            *(float2*)(C + (size_t)row * ldc + col)       = make_float2(acc[i][j][0], acc[i][j][1]);
            *(float2*)(C + (size_t)(row + 8) * ldc + col) = make_float2(acc[i][j][2], acc[i][j][3]);
        }
    }
}

// ---------------- fused window attention: val hi-only, 4-chain phase 2 -----
#define VSTRIDE 72       // halfs per val row (144 B)
#define PBSTRIDE 104     // halfs per PB row (208 B, 16B-multiple); 96 cols used

__global__ __launch_bounds__(512, 2) void fused_kernel(
    const float* __restrict__ W_strain, const float* __restrict__ W_dmg,
    const float* __restrict__ b_dmg,    const float* __restrict__ W_bond,
    const float* __restrict__ W_dmg_out, const float* __restrict__ b_dmg_out)
{
    __shared__ __align__(16) __half s_vh[96 * VSTRIDE];    // 13.5 KB
    __shared__ float   s_disp[NROWS * BD];                 // 6.1 KB
    __shared__ float2  s_W2 [BD * 16];                     // 2 KB
    __shared__ __half2 s_PT [16 * NROWS];                  // 6.1 KB  [c][r]
    __shared__ __half2 s_ppT[16 * DELTA];                  // 4 KB    [c][j]
    __shared__ __align__(16) __half s_PBh[TTILE * PBSTRIDE]; // 6.5 KB
    __shared__ __align__(16) __half s_PBl[TTILE * PBSTRIDE]; // 6.5 KB
    __shared__ __half2 s_wout2[16];
    __shared__ float   s_inv[TTILE];

    const int b  = blockIdx.z;
    const int h  = blockIdx.y;
    const int t0 = blockIdx.x * TTILE;
    const int tid = threadIdx.x;
    const int base_s = t0 - (DELTA - 1);

    // ---- phase 0: loads + zero-init ----
    for (int i = tid; i < NROWS * (HS / 4); i += 512) {
        int r  = i >> 4;
        int c4 = (i & 15) * 4;
        int s  = base_s + r;
        float4 v = make_float4(0.f, 0.f, 0.f, 0.f);
        if (s >= 0)
            v = *(const float4*)(g_dv + (size_t)(b * SEQ + s) * NDV + 256 + h * HS + c4);
        __half2 a = __floats2half2_rn(v.x, v.y);
        __half2 bb = __floats2half2_rn(v.z, v.w);
        *(uint2*)(&s_vh[r * VSTRIDE + c4]) =
            make_uint2(*reinterpret_cast<uint32_t*>(&a), *reinterpret_cast<uint32_t*>(&bb));
    }
    if (tid < 32)    // zero pad row 95 of val window
        *(uint32_t*)(&s_vh[95 * VSTRIDE + tid * 2]) = 0;
    for (int i = tid; i < (TTILE * PBSTRIDE) / 2; i += 512) {
        *(uint32_t*)(&s_PBh[2 * i]) = 0;
        *(uint32_t*)(&s_PBl[2 * i]) = 0;
    }
    for (int i = tid; i < NROWS * (BD / 4); i += 512) {
        int r  = i >> 2;
        int c4 = (i & 3) * 4;
        int s  = base_s + r;
        float4 v = make_float4(0.f, 0.f, 0.f, 0.f);
        if (s >= 0)
            v = *(const float4*)(g_dv + (size_t)(b * SEQ + s) * NDV + h * BD + c4);
        *(float4*)(s_disp + r * BD + c4) = v;
    }
    if (tid < BD * 16)
        s_W2[tid] = make_float2(W_strain[tid], W_dmg[tid]);
    if (tid < 16)
        s_wout2[tid] = __floats2half2_rn(W_bond[tid], W_dmg_out[tid]);
    for (int i = tid; i < 16 * DELTA; i += 512) {
        int c = i >> 6, j = i & 63;
        s_ppT[i] = __floats2half2_rn(g_pos[j * BD + c], b_dmg[c]);
    }
    __syncthreads();

    // ---- phase 1: PT[c][r] = (disp_r . Ws_c, disp_r . Wd_c) as half2 ----
    for (int i = tid; i < NROWS * 16; i += 512) {
        int r = i >> 4, c = i & 15;
        u64 acc = 0;
#pragma unroll
        for (int k = 0; k < BD; k++)
            acc = pd_fma2(pd_dupf(s_disp[r * BD + k]), *(const u64*)(&s_W2[k * 16 + c]), acc);
        float sx, sy; pd_unpack2(acc, sx, sy);
        s_PT[c * NROWS + r] = __floats2half2_rn(sx, sy);
    }
    __syncthreads();

    // ---- phase 2: logits, 4 chains per c iteration ----
    const int wid  = tid >> 5;
    const int lane = tid & 31;

    // gelu(x) = x*(0.5 + x*(G1 + G2*x^2)); exact to <2e-5 for |x|<0.5
    const __half2 G1h = __float2half2_rn(0.3989423f);
    const __half2 G2h = __float2half2_rn(-0.0664904f);
    const __half2 H05 = __float2half2_rn(0.5f);
    const float c0  = 0.5f * b_dmg_out[0];
    const float L2E = 1.44269504089f, N5L2E = -7.21347520444f;

    __half2 accA0 = __float2half2_rn(0.f);
    __half2 accB0 = accA0, accA1 = accA0, accB1 = accA0;

#pragma unroll
    for (int c = 0; c < 16; c++) {
        const __half2* Pc  = &s_PT[c * NROWS];
        const __half2* ppc = &s_ppT[c * DELTA];
        const __half2 ppA = ppc[lane];
        const __half2 ppB = ppc[lane + 32];
        const __half2 pre0 = Pc[wid + DELTA - 1];
        const __half2 pre1 = Pc[wid + 16 + DELTA - 1];
        const __half2 w2  = s_wout2[c];

        __half2 xA0 = __hsub2(__hadd2(Pc[wid + lane],      ppA), pre0);
        __half2 xB0 = __hsub2(__hadd2(Pc[wid + 32 + lane], ppB), pre0);
        __half2 xA1 = __hsub2(__hadd2(Pc[wid + 16 + lane], ppA), pre1);
        __half2 xB1 = __hsub2(__hadd2(Pc[wid + 48 + lane], ppB), pre1);

        __half2 qA0 = __hfma2(xA0, __hfma2(__hmul2(xA0, xA0), G2h, G1h), H05);
        __half2 qB0 = __hfma2(xB0, __hfma2(__hmul2(xB0, xB0), G2h, G1h), H05);
        __half2 qA1 = __hfma2(xA1, __hfma2(__hmul2(xA1, xA1), G2h, G1h), H05);
        __half2 qB1 = __hfma2(xB1, __hfma2(__hmul2(xB1, xB1), G2h, G1h), H05);

        accA0 = __hfma2(__hmul2(xA0, qA0), w2, accA0);
        accB0 = __hfma2(__hmul2(xB0, qB0), w2, accB0);
        accA1 = __hfma2(__hmul2(xA1, qA1), w2, accA1);
        accB1 = __hfma2(__hmul2(xB1, qB1), w2, accB1);
    }

#pragma unroll
    for (int half_t = 0; half_t < 2; half_t++) {
        const int tt = wid + half_t * 16;
        const int t  = t0 + tt;
        const int jstart = (t < DELTA - 1) ? (DELTA - 1 - t) : 0;
        const __half2 aA = half_t ? accA1 : accA0;
        const __half2 aB = half_t ? accB1 : accB0;

        float p0, p1;
        {
            float bond = __low2float(aA), dm = __high2float(aA);
            float th2 = pd_tanhf(fmaf(dm, 0.5f, c0));
            float lt  = fmaf(th2, -5.f, bond);
            p0 = pd_ex2(fmaf(lt, L2E, N5L2E));
            if (lane < jstart) p0 = 0.f;
        }
        {
            float bond = __low2float(aB), dm = __high2float(aB);
            float th2 = pd_tanhf(fmaf(dm, 0.5f, c0));
            float lt  = fmaf(th2, -5.f, bond);
            p1 = pd_ex2(fmaf(lt, L2E, N5L2E));
            if (lane + 32 < jstart) p1 = 0.f;
        }

        {
            __half ph0 = __float2half_rn(p0);
            __half pl0 = __float2half_rn(p0 - __half2float(ph0));
            __half ph1 = __float2half_rn(p1);
            __half pl1 = __float2half_rn(p1 - __half2float(ph1));
            int bcol = tt * PBSTRIDE + tt + lane;
            s_PBh[bcol] = ph0;       s_PBl[bcol] = pl0;
            s_PBh[bcol + 32] = ph1;  s_PBl[bcol + 32] = pl1;
        }

        float ssum = p0 + p1;
#pragma unroll
        for (int off = 1; off < 32; off <<= 1)
            ssum += __shfl_xor_sync(0xffffffffu, ssum, off);
        if (lane == 0)
            s_inv[tt] = __fdividef(1.0f, ssum);
    }
    __syncthreads();

    // ---- phase 3: out[32][64] = PB[32][96] x val[96][64]; 16 warps ----
    {
        const int mhalf = wid >> 3;          // 0: t rows 0-15, 1: rows 16-31
        const int nb    = wid & 7;           // 8-col output block
        const int rowbase = mhalf * 16;
        float acc[4] = {0.f, 0.f, 0.f, 0.f};
        const uint32_t pbh = pd_smem_u32(s_PBh), pbl = pd_smem_u32(s_PBl);
        const uint32_t vhb = pd_smem_u32(s_vh);
        const uint32_t rA = (uint32_t)(lane & 15);
        const uint32_t cA = (uint32_t)((lane >> 4) * 8);
#pragma unroll
        for (int kk = 0; kk < 5; kk++) {
            uint32_t offA = ((rowbase + rA) * PBSTRIDE + rowbase + kk * 16 + cA) * 2;
            uint32_t offB = ((rowbase + kk * 16 + (lane & 15)) * VSTRIDE + nb * 8) * 2;
            uint32_t Ah[4], Al[4], Bh[2];
            PD_LDSM_X4(Ah, pbh + offA);
            PD_LDSM_X4(Al, pbl + offA);
            PD_LDSM_X2T(Bh, vhb + offB);
            pd_mma_fp16(acc, Ah, Bh);
            pd_mma_fp16(acc, Al, Bh);
        }
        const int r0 = lane >> 2;
        const int e  = nb * 8 + (lane & 3) * 2;
        const float inv0 = s_inv[rowbase + r0], inv1 = s_inv[rowbase + r0 + 8];
        size_t ob0 = (size_t)(b * SEQ + t0 + rowbase + r0) * EMB + h * HS + e;
        *(__half2*)(&g_athi[ob0]) = __floats2half2_rn(acc[0] * inv0, acc[1] * inv0);
        size_t ob1 = ob0 + (size_t)8 * EMB;
        *(__half2*)(&g_athi[ob1]) = __floats2half2_rn(acc[2] * inv1, acc[3] * inv1);
    }
}

// ---------------- launch ----------------
extern "C" void kernel_launch(void* const* d_in, const int* in_sizes, int n_in,
                              void* d_out, int out_size)
{
    const float* x         = (const float*)d_in[0];
    const float* W_disp    = (const float*)d_in[1];
    const float* W_val     = (const float*)d_in[2];
    const float* rel       = (const float*)d_in[3];
    const float* W_strain  = (const float*)d_in[4];
    const float* W_pos     = (const float*)d_in[5];
    const float* W_bond    = (const float*)d_in[6];
    const float* W_dmg     = (const float*)d_in[7];
    const float* b_dmg     = (const float*)d_in[8];
    const float* W_dmg_out = (const float*)d_in[9];
    const float* b_dmg_out = (const float*)d_in[10];
    const float* W_cproj   = (const float*)d_in[11];
    float* out = (float*)d_out;

    float* dv_p;
    __half *xhi, *athi, *bthi, *cthi;
    cudaGetSymbolAddress((void**)&dv_p, g_dv);
    cudaGetSymbolAddress((void**)&xhi, g_xhi);
    cudaGetSymbolAddress((void**)&athi, g_athi);
    cudaGetSymbolAddress((void**)&bthi, g_bthi);
    cudaGetSymbolAddress((void**)&cthi, g_cthi);

    const int SMEM_DV = (128 + 160) * ROWB * 2;   // 156672
    const int SMEM_CP = (128 + 128) * ROWB * 2;   // 139264
    cudaFuncSetAttribute((const void*)gemm_kernel<128, 160, 512, 4>,
                         cudaFuncAttributeMaxDynamicSharedMemorySize, SMEM_DV);
    cudaFuncSetAttribute((const void*)gemm_kernel<128, 128, 512, 4>,
                         cudaFuncAttributeMaxDynamicSharedMemorySize, SMEM_CP);

    split_x_kernel<<<(MTOT * EMB / 4) / 512, 512>>>(x);
    splitT_kernel<<<dim3(2304 / 32, EMB / 32), dim3(32, 8)>>>(W_disp, W_val, W_cproj, rel, W_pos);

    gemm_kernel<128, 160, 512, 4><<<dim3(NDV / 160, MTOT / 128), 512, SMEM_DV>>>(
        xhi, bthi, dv_p, NDV);
    fused_kernel<<<dim3(SEQ / TTILE, NH, BATCH), 512>>>(W_strain, W_dmg, b_dmg,
                                                        W_bond, W_dmg_out, b_dmg_out);
    gemm_kernel<128, 128, 512, 4><<<dim3(EMB / 128, MTOT / 128), 512, SMEM_CP>>>(
        athi, cthi, out, EMB);
}